// round 1
// baseline (speedup 1.0000x reference)
#include <cuda_runtime.h>
#include <math.h>

#define B_DIM 32
#define T_DIM 2048
#define H_DIM 1024

// Scratch (allocation-free rule: __device__ globals)
__device__ float g_qproj[B_DIM * H_DIM];
__device__ float g_score[B_DIM * T_DIM];

// ---------------------------------------------------------------------------
// Kernel 1: q_proj[b][o] = dot(query[b,:], Wq[o,:]) + bq[o]
// grid = B, block = 256 (8 warps). Warp-per-output with shuffle reduce.
// ---------------------------------------------------------------------------
__global__ void qproj_kernel(const float* __restrict__ query,
                             const float* __restrict__ Wq,
                             const float* __restrict__ bq) {
    __shared__ float q_s[H_DIM];
    const int b = blockIdx.x;
    const int tid = threadIdx.x;
    for (int i = tid; i < H_DIM; i += 256) q_s[i] = query[b * H_DIM + i];
    __syncthreads();

    const int warp = tid >> 5;
    const int lane = tid & 31;
    for (int o = warp; o < H_DIM; o += 8) {
        const float* wrow = Wq + (size_t)o * H_DIM;
        float s = 0.f;
        #pragma unroll 8
        for (int h = lane; h < H_DIM; h += 32) s += q_s[h] * wrow[h];
        #pragma unroll
        for (int m = 16; m > 0; m >>= 1) s += __shfl_xor_sync(0xffffffffu, s, m);
        if (lane == 0) g_qproj[b * H_DIM + o] = s + bq[o];
    }
}

// ---------------------------------------------------------------------------
// Kernel 2: fused score GEMM.
//   score[r] = Vb + sum_o Vw[o] * tanh(qproj[b][o] + bv[o] + sum_k V[r][k]*Wv[o][k])
// r = b*T + t (65536 rows). Block = 128-row tile, loops over 8 o-chunks of 128.
// Classic 128x128 SGEMM tiling: 256 threads, 8x8 micro-tiles, k-tile = 16.
// Epilogue folds tanh + Vw into per-row partial sums (shuffle reduce over tx).
// v_proj never touches HBM.
// ---------------------------------------------------------------------------
__global__ void __launch_bounds__(256, 2) score_kernel(
    const float* __restrict__ values,
    const float* __restrict__ Wv,
    const float* __restrict__ bv,
    const float* __restrict__ Vw,
    const float* __restrict__ Vb) {

    __shared__ float As[16][128];   // k-major values tile
    __shared__ float Bs[16][128];   // k-major Wv tile
    __shared__ float score_s[128];
    __shared__ float qb_s[128];     // qproj + bv for current o-chunk
    __shared__ float vw_s[128];

    const int tid = threadIdx.x;
    const int r0  = blockIdx.x * 128;         // global row base (b*T + t)
    const int b   = r0 / T_DIM;               // tiles never straddle b (2048 % 128 == 0)
    const float* qp = g_qproj + b * H_DIM;

    if (tid < 128) score_s[tid] = 0.f;

    const int lr = tid >> 1;                  // load row/owner 0..127
    const int kq = (tid & 1) * 8;             // 8-float (32B) chunk per thread
    const int ty = tid >> 4;                  // 0..15
    const int tx = tid & 15;                  // 0..15

    for (int oc = 0; oc < 8; ++oc) {
        const int ob = oc * 128;
        __syncthreads();                      // protect qb_s/vw_s from prev epilogue
        if (tid < 128) {
            qb_s[tid] = qp[ob + tid] + bv[ob + tid];
            vw_s[tid] = Vw[ob + tid];
        }
        __syncthreads();

        float acc[8][8];
        #pragma unroll
        for (int i = 0; i < 8; ++i)
            #pragma unroll
            for (int j = 0; j < 8; ++j) acc[i][j] = 0.f;

        for (int k0 = 0; k0 < H_DIM; k0 += 16) {
            const float4* ga = (const float4*)(values + (size_t)(r0 + lr) * H_DIM + k0 + kq);
            float4 a0 = ga[0], a1 = ga[1];
            const float4* gb = (const float4*)(Wv + (size_t)(ob + lr) * H_DIM + k0 + kq);
            float4 w0 = gb[0], w1 = gb[1];

            As[kq + 0][lr] = a0.x; As[kq + 1][lr] = a0.y;
            As[kq + 2][lr] = a0.z; As[kq + 3][lr] = a0.w;
            As[kq + 4][lr] = a1.x; As[kq + 5][lr] = a1.y;
            As[kq + 6][lr] = a1.z; As[kq + 7][lr] = a1.w;

            Bs[kq + 0][lr] = w0.x; Bs[kq + 1][lr] = w0.y;
            Bs[kq + 2][lr] = w0.z; Bs[kq + 3][lr] = w0.w;
            Bs[kq + 4][lr] = w1.x; Bs[kq + 5][lr] = w1.y;
            Bs[kq + 6][lr] = w1.z; Bs[kq + 7][lr] = w1.w;
            __syncthreads();

            #pragma unroll
            for (int k = 0; k < 16; ++k) {
                float4 av0 = *(const float4*)&As[k][ty * 4];
                float4 av1 = *(const float4*)&As[k][64 + ty * 4];
                float4 bv0 = *(const float4*)&Bs[k][tx * 4];
                float4 bv1 = *(const float4*)&Bs[k][64 + tx * 4];
                float a[8] = {av0.x, av0.y, av0.z, av0.w, av1.x, av1.y, av1.z, av1.w};
                float w[8] = {bv0.x, bv0.y, bv0.z, bv0.w, bv1.x, bv1.y, bv1.z, bv1.w};
                #pragma unroll
                for (int i = 0; i < 8; ++i)
                    #pragma unroll
                    for (int j = 0; j < 8; ++j)
                        acc[i][j] = fmaf(a[i], w[j], acc[i][j]);
            }
            __syncthreads();
        }

        // Epilogue: tanh + Vw contraction, reduce 8 cols in-thread, then over tx.
        #pragma unroll
        for (int i = 0; i < 8; ++i) {
            float p = 0.f;
            #pragma unroll
            for (int j = 0; j < 8; ++j) {
                const int col = (j < 4) ? (tx * 4 + j) : (64 + tx * 4 + (j - 4));
                p += vw_s[col] * tanhf(acc[i][j] + qb_s[col]);
            }
            // reduce over tx (16 lanes within each warp half; ty constant there)
            #pragma unroll
            for (int m = 1; m < 16; m <<= 1) p += __shfl_xor_sync(0xffffffffu, p, m);
            if (tx == 0) {
                const int row = (i < 4) ? (ty * 4 + i) : (64 + ty * 4 + (i - 4));
                score_s[row] += p;   // unique writer per row
            }
        }
    }
    __syncthreads();
    if (tid < 128) g_score[r0 + tid] = score_s[tid] + Vb[0];
}

// ---------------------------------------------------------------------------
// Kernel 3: softmax over T per batch. Writes weights into d_out[B*H ..].
// ---------------------------------------------------------------------------
__global__ void softmax_kernel(float* __restrict__ d_out) {
    __shared__ float red[1024];
    const int b = blockIdx.x;
    const int tid = threadIdx.x;   // 1024
    const float s0 = g_score[b * T_DIM + tid];
    const float s1 = g_score[b * T_DIM + 1024 + tid];

    red[tid] = fmaxf(s0, s1);
    __syncthreads();
    for (int s = 512; s > 0; s >>= 1) {
        if (tid < s) red[tid] = fmaxf(red[tid], red[tid + s]);
        __syncthreads();
    }
    const float mx = red[0];
    __syncthreads();

    const float e0 = expf(s0 - mx);
    const float e1 = expf(s1 - mx);
    red[tid] = e0 + e1;
    __syncthreads();
    for (int s = 512; s > 0; s >>= 1) {
        if (tid < s) red[tid] += red[tid + s];
        __syncthreads();
    }
    const float inv = 1.f / red[0];

    float* w = d_out + B_DIM * H_DIM + b * T_DIM;
    w[tid]        = e0 * inv;
    w[tid + 1024] = e1 * inv;
}

// ---------------------------------------------------------------------------
// Kernel 4: context[b][h] = sum_t w[b][t] * values[b][t][h]
// grid = (8 h-chunks, B). 128 threads, thread-per-h, 4-way ILP over t.
// ---------------------------------------------------------------------------
__global__ void __launch_bounds__(128) context_kernel(
    const float* __restrict__ values, float* __restrict__ d_out) {
    __shared__ float w_s[T_DIM];
    const int b  = blockIdx.y;
    const int hc = blockIdx.x;
    const int tid = threadIdx.x;
    const float* w = d_out + B_DIM * H_DIM + b * T_DIM;
    for (int i = tid; i < T_DIM; i += 128) w_s[i] = w[i];
    __syncthreads();

    const int h = hc * 128 + tid;
    const float* vp = values + (size_t)b * T_DIM * H_DIM + h;
    float a0 = 0.f, a1 = 0.f, a2 = 0.f, a3 = 0.f;
    #pragma unroll 2
    for (int t = 0; t < T_DIM; t += 4) {
        a0 += w_s[t + 0] * vp[(size_t)(t + 0) * H_DIM];
        a1 += w_s[t + 1] * vp[(size_t)(t + 1) * H_DIM];
        a2 += w_s[t + 2] * vp[(size_t)(t + 2) * H_DIM];
        a3 += w_s[t + 3] * vp[(size_t)(t + 3) * H_DIM];
    }
    d_out[b * H_DIM + h] = (a0 + a1) + (a2 + a3);
}

// ---------------------------------------------------------------------------
extern "C" void kernel_launch(void* const* d_in, const int* in_sizes, int n_in,
                              void* d_out, int out_size) {
    const float* query  = (const float*)d_in[0];
    const float* values = (const float*)d_in[1];
    const float* Wq     = (const float*)d_in[2];
    const float* bq     = (const float*)d_in[3];
    const float* Wv     = (const float*)d_in[4];
    const float* bv     = (const float*)d_in[5];
    const float* Vw     = (const float*)d_in[6];
    const float* Vb     = (const float*)d_in[7];
    float* out = (float*)d_out;

    qproj_kernel<<<B_DIM, 256>>>(query, Wq, bq);
    score_kernel<<<(B_DIM * T_DIM) / 128, 256>>>(values, Wv, bv, Vw, Vb);
    softmax_kernel<<<B_DIM, 1024>>>(out);
    context_kernel<<<dim3(8, B_DIM), 128>>>(values, out);
}

// round 3
// speedup vs baseline: 1.9484x; 1.9484x over previous
#include <cuda_runtime.h>
#include <math.h>
#include <stdint.h>

#define B_DIM 32
#define T_DIM 2048
#define H_DIM 1024

// ---------------------------------------------------------------------------
// Scratch (allocation-free rule: __device__ globals)
// ---------------------------------------------------------------------------
__device__ float g_qproj[B_DIM * H_DIM];
__device__ float g_score[B_DIM * T_DIM];
__device__ float g_ctx_part[B_DIM * 8 * H_DIM];

// ---------------------------------------------------------------------------
// PTX helpers (sm_80-compatible only; tcgen05 is NOT available at compute_103)
// ---------------------------------------------------------------------------
__device__ __forceinline__ uint32_t smem_u32(const void* p) {
    uint32_t a;
    asm("{ .reg .u64 t; cvta.to.shared.u64 t, %1; cvt.u32.u64 %0, t; }" : "=r"(a) : "l"(p));
    return a;
}
__device__ __forceinline__ void cp_async16(uint32_t dst, const void* src) {
    asm volatile("cp.async.cg.shared.global [%0], [%1], 16;" :: "r"(dst), "l"(src));
}
__device__ __forceinline__ void cp_commit() {
    asm volatile("cp.async.commit_group;" ::: "memory");
}
template <int N>
__device__ __forceinline__ void cp_wait() {
    asm volatile("cp.async.wait_group %0;" :: "n"(N) : "memory");
}
__device__ __forceinline__ uint32_t to_tf32(float x) {
    uint32_t r;
    asm("cvt.rna.tf32.f32 %0, %1;" : "=r"(r) : "f"(x));
    return r;
}
__device__ __forceinline__ void mma_tf32(float c[4], const uint32_t a[4], const uint32_t b[2]) {
    asm volatile(
        "mma.sync.aligned.m16n8k8.row.col.f32.tf32.tf32.f32 "
        "{%0,%1,%2,%3}, {%4,%5,%6,%7}, {%8,%9}, {%0,%1,%2,%3};"
        : "+f"(c[0]), "+f"(c[1]), "+f"(c[2]), "+f"(c[3])
        : "r"(a[0]), "r"(a[1]), "r"(a[2]), "r"(a[3]), "r"(b[0]), "r"(b[1]));
}
__device__ __forceinline__ float fast_tanh(float x) {
    float e = __expf(2.0f * x);
    return 1.0f - 2.0f / (e + 1.0f);
}

// ---------------------------------------------------------------------------
// Kernel 1: q_proj[b][o] = dot(query[b,:], Wq[o,:]) + bq[o]   (fp32 exact)
// ---------------------------------------------------------------------------
__global__ void qproj_kernel(const float* __restrict__ query,
                             const float* __restrict__ Wq,
                             const float* __restrict__ bq) {
    __shared__ float q_s[H_DIM];
    const int b = blockIdx.x;
    const int tid = threadIdx.x;
    for (int i = tid; i < H_DIM; i += 256) q_s[i] = query[b * H_DIM + i];
    __syncthreads();
    const int warp = tid >> 5, lane = tid & 31;
    for (int o = warp; o < H_DIM; o += 8) {
        const float* wrow = Wq + (size_t)o * H_DIM;
        float s = 0.f;
        #pragma unroll 8
        for (int h = lane; h < H_DIM; h += 32) s += q_s[h] * wrow[h];
        #pragma unroll
        for (int m = 16; m > 0; m >>= 1) s += __shfl_xor_sync(0xffffffffu, s, m);
        if (lane == 0) g_qproj[b * H_DIM + o] = s + bq[o];
    }
}

// ---------------------------------------------------------------------------
// Kernel 2: fused score GEMM on tf32 mma.sync.
//   score[r] = Vb + sum_o Vw[o]*tanh(qproj[b][o]+bv[o] + sum_k V[r][k]*Wv[o][k])
// Block: 128 rows (r), loops 8 o-chunks of 128. 256 threads = 8 warps (4m x 2n),
// warp tile 32x64 via m16n8k8 tf32 mma. 2-stage cp.async K pipeline (BK=32).
// Per-lane score partials kept in registers across all o-chunks.
// ---------------------------------------------------------------------------
#define BK       32
#define LDP      36                            // padded row stride (floats)
#define ST_FLTS  (128 * LDP)                   // one tile = 4608 floats
#define OFF_A    0
#define OFF_B    (2 * ST_FLTS)
#define OFF_QB   (4 * ST_FLTS)
#define OFF_VW   (4 * ST_FLTS + 128)
#define OFF_SC   (4 * ST_FLTS + 256)
#define SMEM_FLT (4 * ST_FLTS + 384)
#define SMEM_BYTES (SMEM_FLT * 4)

__device__ __forceinline__ void load_tile(float* dst, const float* __restrict__ src,
                                          int k0, int tid) {
    // 128 rows x 32 floats (8 x 16B chunks per row); 256 threads, 4 chunks each
    #pragma unroll
    for (int it = 0; it < 4; ++it) {
        int idx = it * 256 + tid;
        int row = idx >> 3, ch = idx & 7;
        cp_async16(smem_u32(dst + row * LDP + ch * 4),
                   src + (size_t)row * H_DIM + k0 + ch * 4);
    }
}

__global__ void __launch_bounds__(256, 2) score_kernel(
    const float* __restrict__ values,
    const float* __restrict__ Wv,
    const float* __restrict__ bv,
    const float* __restrict__ Vw,
    const float* __restrict__ Vb) {

    extern __shared__ __align__(16) float smem[];
    float* As = smem + OFF_A;            // [2][128][36]
    float* Bs = smem + OFF_B;
    float* qb_s = smem + OFF_QB;
    float* vw_s = smem + OFF_VW;
    float* score_s = smem + OFF_SC;

    const int tid = threadIdx.x;
    const int wid = tid >> 5, lane = tid & 31;
    const int warp_m = wid >> 1, warp_n = wid & 1;   // 4 x 2
    const int gid = lane >> 2, tig = lane & 3;

    const int r0 = blockIdx.x * 128;
    const int b  = r0 / T_DIM;
    const float* qp = g_qproj + b * H_DIM;
    const float* vrow0 = values + (size_t)r0 * H_DIM;

    if (tid < 128) score_s[tid] = 0.f;

    float sacc[4] = {0.f, 0.f, 0.f, 0.f};   // [mt*2 + rowhalf]

    for (int oc = 0; oc < 8; ++oc) {
        const int ob = oc * 128;
        __syncthreads();                       // prev pass fully done
        if (tid < 128) {
            qb_s[tid] = qp[ob + tid] + bv[ob + tid];
            vw_s[tid] = Vw[ob + tid];
        }

        float c[2][8][4];
        #pragma unroll
        for (int mt = 0; mt < 2; ++mt)
            #pragma unroll
            for (int nt = 0; nt < 8; ++nt)
                #pragma unroll
                for (int i = 0; i < 4; ++i) c[mt][nt][i] = 0.f;

        // prologue
        load_tile(As, vrow0, 0, tid);
        load_tile(Bs, Wv + (size_t)ob * H_DIM, 0, tid);
        cp_commit();

        for (int kt = 0; kt < H_DIM / BK; ++kt) {
            const int cur = kt & 1;
            if (kt + 1 < H_DIM / BK) {
                const int nxt = cur ^ 1;
                load_tile(As + nxt * ST_FLTS, vrow0, (kt + 1) * BK, tid);
                load_tile(Bs + nxt * ST_FLTS, Wv + (size_t)ob * H_DIM, (kt + 1) * BK, tid);
                cp_commit();
                cp_wait<1>();
            } else {
                cp_wait<0>();
            }
            __syncthreads();

            const float* Ac = As + cur * ST_FLTS;
            const float* Bc = Bs + cur * ST_FLTS;
            #pragma unroll
            for (int ks = 0; ks < 4; ++ks) {
                const int k0 = ks * 8;
                uint32_t af[2][4], bf[8][2];
                #pragma unroll
                for (int mt = 0; mt < 2; ++mt) {
                    const int row = warp_m * 32 + mt * 16 + gid;
                    af[mt][0] = to_tf32(Ac[row * LDP + k0 + tig]);
                    af[mt][1] = to_tf32(Ac[(row + 8) * LDP + k0 + tig]);
                    af[mt][2] = to_tf32(Ac[row * LDP + k0 + tig + 4]);
                    af[mt][3] = to_tf32(Ac[(row + 8) * LDP + k0 + tig + 4]);
                }
                #pragma unroll
                for (int nt = 0; nt < 8; ++nt) {
                    const int nrow = warp_n * 64 + nt * 8 + gid;
                    bf[nt][0] = to_tf32(Bc[nrow * LDP + k0 + tig]);
                    bf[nt][1] = to_tf32(Bc[nrow * LDP + k0 + tig + 4]);
                }
                #pragma unroll
                for (int mt = 0; mt < 2; ++mt)
                    #pragma unroll
                    for (int nt = 0; nt < 8; ++nt)
                        mma_tf32(c[mt][nt], af[mt], bf[nt]);
            }
            __syncthreads();  // all warps done with cur before it is reloaded
        }

        // Epilogue: tanh + Vw contraction into per-lane row partials
        #pragma unroll
        for (int nt = 0; nt < 8; ++nt) {
            const int col0 = warp_n * 64 + nt * 8 + 2 * tig;
            const float vw0 = vw_s[col0],     qb0 = qb_s[col0];
            const float vw1 = vw_s[col0 + 1], qb1 = qb_s[col0 + 1];
            #pragma unroll
            for (int mt = 0; mt < 2; ++mt) {
                sacc[mt * 2 + 0] += vw0 * fast_tanh(c[mt][nt][0] + qb0)
                                  + vw1 * fast_tanh(c[mt][nt][1] + qb1);
                sacc[mt * 2 + 1] += vw0 * fast_tanh(c[mt][nt][2] + qb0)
                                  + vw1 * fast_tanh(c[mt][nt][3] + qb1);
            }
        }
    }

    // reduce over the 4 tig lanes, then combine warp_n halves via smem atomics
    #pragma unroll
    for (int i = 0; i < 4; ++i) {
        sacc[i] += __shfl_xor_sync(0xffffffffu, sacc[i], 1);
        sacc[i] += __shfl_xor_sync(0xffffffffu, sacc[i], 2);
    }
    if (tig == 0) {
        #pragma unroll
        for (int i = 0; i < 4; ++i) {
            const int row = warp_m * 32 + (i >> 1) * 16 + gid + (i & 1) * 8;
            atomicAdd(&score_s[row], sacc[i]);
        }
    }
    __syncthreads();
    if (tid < 128) g_score[r0 + tid] = score_s[tid] + Vb[0];
}

// ---------------------------------------------------------------------------
// Kernel 3: softmax over T per batch. Writes weights into d_out[B*H ..].
// ---------------------------------------------------------------------------
__global__ void softmax_kernel(float* __restrict__ d_out) {
    __shared__ float red[1024];
    const int b = blockIdx.x;
    const int tid = threadIdx.x;
    const float s0 = g_score[b * T_DIM + tid];
    const float s1 = g_score[b * T_DIM + 1024 + tid];
    red[tid] = fmaxf(s0, s1);
    __syncthreads();
    for (int s = 512; s > 0; s >>= 1) {
        if (tid < s) red[tid] = fmaxf(red[tid], red[tid + s]);
        __syncthreads();
    }
    const float mx = red[0];
    __syncthreads();
    const float e0 = expf(s0 - mx), e1 = expf(s1 - mx);
    red[tid] = e0 + e1;
    __syncthreads();
    for (int s = 512; s > 0; s >>= 1) {
        if (tid < s) red[tid] += red[tid + s];
        __syncthreads();
    }
    const float inv = 1.f / red[0];
    float* w = d_out + B_DIM * H_DIM + b * T_DIM;
    w[tid] = e0 * inv;
    w[tid + 1024] = e1 * inv;
}

// ---------------------------------------------------------------------------
// Kernel 4a: context partials over T chunks; 4b: deterministic reduce.
// ---------------------------------------------------------------------------
__global__ void __launch_bounds__(1024) ctx_partial_kernel(
    const float* __restrict__ values, const float* __restrict__ d_out_w) {
    __shared__ float w_s[256];
    const int ts = blockIdx.x, b = blockIdx.y;
    const int h = threadIdx.x;
    const float* w = d_out_w + b * T_DIM + ts * 256;
    if (h < 256) w_s[h] = w[h];
    __syncthreads();
    const float* vp = values + ((size_t)b * T_DIM + ts * 256) * H_DIM + h;
    float a0 = 0.f, a1 = 0.f, a2 = 0.f, a3 = 0.f;
    #pragma unroll 4
    for (int t = 0; t < 256; t += 4) {
        a0 += w_s[t + 0] * vp[(size_t)(t + 0) * H_DIM];
        a1 += w_s[t + 1] * vp[(size_t)(t + 1) * H_DIM];
        a2 += w_s[t + 2] * vp[(size_t)(t + 2) * H_DIM];
        a3 += w_s[t + 3] * vp[(size_t)(t + 3) * H_DIM];
    }
    g_ctx_part[(b * 8 + ts) * H_DIM + h] = (a0 + a1) + (a2 + a3);
}

__global__ void __launch_bounds__(1024) ctx_reduce_kernel(float* __restrict__ d_out) {
    const int b = blockIdx.x, h = threadIdx.x;
    float s = 0.f;
    #pragma unroll
    for (int ts = 0; ts < 8; ++ts) s += g_ctx_part[(b * 8 + ts) * H_DIM + h];
    d_out[b * H_DIM + h] = s;
}

// ---------------------------------------------------------------------------
extern "C" void kernel_launch(void* const* d_in, const int* in_sizes, int n_in,
                              void* d_out, int out_size) {
    const float* query  = (const float*)d_in[0];
    const float* values = (const float*)d_in[1];
    const float* Wq     = (const float*)d_in[2];
    const float* bq     = (const float*)d_in[3];
    const float* Wv     = (const float*)d_in[4];
    const float* bv     = (const float*)d_in[5];
    const float* Vw     = (const float*)d_in[6];
    const float* Vb     = (const float*)d_in[7];
    float* out = (float*)d_out;

    static bool attr_set = false;
    if (!attr_set) {
        cudaFuncSetAttribute(score_kernel, cudaFuncAttributeMaxDynamicSharedMemorySize,
                             SMEM_BYTES);
        attr_set = true;
    }

    qproj_kernel<<<B_DIM, 256>>>(query, Wq, bq);
    score_kernel<<<(B_DIM * T_DIM) / 128, 256, SMEM_BYTES>>>(values, Wv, bv, Vw, Vb);
    softmax_kernel<<<B_DIM, 1024>>>(out);
    ctx_partial_kernel<<<dim3(8, B_DIM), 1024>>>(values, out + B_DIM * H_DIM);
    ctx_reduce_kernel<<<B_DIM, 1024>>>(out);
}

// round 4
// speedup vs baseline: 3.2007x; 1.6427x over previous
#include <cuda_runtime.h>
#include <math.h>
#include <stdint.h>

#define B_DIM 32
#define T_DIM 2048
#define H_DIM 1024

// ---------------------------------------------------------------------------
// Scratch (allocation-free rule: __device__ globals)
// ---------------------------------------------------------------------------
__device__ float g_qproj[B_DIM * H_DIM];
__device__ float g_score[B_DIM * T_DIM];
__device__ float g_ctx_part[B_DIM * 8 * H_DIM];

// ---------------------------------------------------------------------------
// PTX helpers (sm_80-compatible; tcgen05 is NOT available at compute_103)
// ---------------------------------------------------------------------------
__device__ __forceinline__ uint32_t smem_u32(const void* p) {
    uint32_t a;
    asm("{ .reg .u64 t; cvta.to.shared.u64 t, %1; cvt.u32.u64 %0, t; }" : "=r"(a) : "l"(p));
    return a;
}
__device__ __forceinline__ void cp_async16(uint32_t dst, const void* src) {
    asm volatile("cp.async.cg.shared.global [%0], [%1], 16;" :: "r"(dst), "l"(src));
}
__device__ __forceinline__ void cp_commit() {
    asm volatile("cp.async.commit_group;" ::: "memory");
}
template <int N>
__device__ __forceinline__ void cp_wait() {
    asm volatile("cp.async.wait_group %0;" :: "n"(N) : "memory");
}
__device__ __forceinline__ void ldsm_x4(uint32_t r[4], uint32_t addr) {
    asm volatile("ldmatrix.sync.aligned.m8n8.x4.shared.b16 {%0,%1,%2,%3}, [%4];"
                 : "=r"(r[0]), "=r"(r[1]), "=r"(r[2]), "=r"(r[3]) : "r"(addr));
}
__device__ __forceinline__ void mma_tf32(float c[4], const uint32_t a[4], const uint32_t b[2]) {
    asm volatile(
        "mma.sync.aligned.m16n8k8.row.col.f32.tf32.tf32.f32 "
        "{%0,%1,%2,%3}, {%4,%5,%6,%7}, {%8,%9}, {%0,%1,%2,%3};"
        : "+f"(c[0]), "+f"(c[1]), "+f"(c[2]), "+f"(c[3])
        : "r"(a[0]), "r"(a[1]), "r"(a[2]), "r"(a[3]), "r"(b[0]), "r"(b[1]));
}
__device__ __forceinline__ float fast_tanh(float x) {
    float e = __expf(2.0f * x);
    return 1.0f - 2.0f / (e + 1.0f);
}

// ---------------------------------------------------------------------------
// Kernel 1: q_proj[b][o] = dot(query[b,:], Wq[o,:]) + bq[o]   (fp32 exact)
// ---------------------------------------------------------------------------
__global__ void qproj_kernel(const float* __restrict__ query,
                             const float* __restrict__ Wq,
                             const float* __restrict__ bq) {
    __shared__ float q_s[H_DIM];
    const int b = blockIdx.x;
    const int tid = threadIdx.x;
    for (int i = tid; i < H_DIM; i += 256) q_s[i] = query[b * H_DIM + i];
    __syncthreads();
    const int warp = tid >> 5, lane = tid & 31;
    for (int o = warp; o < H_DIM; o += 8) {
        const float* wrow = Wq + (size_t)o * H_DIM;
        float s = 0.f;
        #pragma unroll 8
        for (int h = lane; h < H_DIM; h += 32) s += q_s[h] * wrow[h];
        #pragma unroll
        for (int m = 16; m > 0; m >>= 1) s += __shfl_xor_sync(0xffffffffu, s, m);
        if (lane == 0) g_qproj[b * H_DIM + o] = s + bq[o];
    }
}

// ---------------------------------------------------------------------------
// Kernel 2: fused score GEMM on tf32 mma.sync with ldmatrix fragment loads.
//   score[r] = Vb + sum_o Vw[o]*tanh(qproj[b][o]+bv[o] + sum_k V[r][k]*Wv[o][k])
// Block: 128 rows, 8 o-chunks of 128. 256 threads = 8 warps (4m x 2n),
// warp tile 32x64. 2-stage cp.async pipeline (BK=32). Raw fp32 bits fed to
// tf32 HMMA (hardware truncates mantissa).
// ---------------------------------------------------------------------------
#define BK       32
#define LDP      36                            // padded row stride (floats)
#define ST_FLTS  (128 * LDP)
#define OFF_A    0
#define OFF_B    (2 * ST_FLTS)
#define OFF_QB   (4 * ST_FLTS)
#define OFF_VW   (4 * ST_FLTS + 128)
#define OFF_SC   (4 * ST_FLTS + 256)
#define SMEM_FLT (4 * ST_FLTS + 384)
#define SMEM_BYTES (SMEM_FLT * 4)

__device__ __forceinline__ void load_tile(float* dst, const float* __restrict__ src,
                                          int k0, int tid) {
    #pragma unroll
    for (int it = 0; it < 4; ++it) {
        int idx = it * 256 + tid;
        int row = idx >> 3, ch = idx & 7;
        cp_async16(smem_u32(dst + row * LDP + ch * 4),
                   src + (size_t)row * H_DIM + k0 + ch * 4);
    }
}

__global__ void __launch_bounds__(256, 2) score_kernel(
    const float* __restrict__ values,
    const float* __restrict__ Wv,
    const float* __restrict__ bv,
    const float* __restrict__ Vw,
    const float* __restrict__ Vb) {

    extern __shared__ __align__(16) float smem[];
    float* As = smem + OFF_A;            // [2][128][36]
    float* Bs = smem + OFF_B;
    float* qb_s = smem + OFF_QB;
    float* vw_s = smem + OFF_VW;
    float* score_s = smem + OFF_SC;

    const int tid = threadIdx.x;
    const int wid = tid >> 5, lane = tid & 31;
    const int warp_m = wid >> 1, warp_n = wid & 1;   // 4 x 2
    const int gid = lane >> 2, tig = lane & 3;
    const int l8 = lane & 7, sel = lane >> 3;        // ldmatrix addressing

    const int r0 = blockIdx.x * 128;
    const int b  = r0 / T_DIM;
    const float* qp = g_qproj + b * H_DIM;
    const float* vrow0 = values + (size_t)r0 * H_DIM;

    if (tid < 128) score_s[tid] = 0.f;

    // ldmatrix lane-row offsets (in floats), relative to tile base + k0
    //  A (.x4): m0 rows r0..r0+7 k, m1 rows +8 k, m2 rows k+4, m3 rows +8 k+4
    const int a_row = warp_m * 32 + ((sel & 1) ? 8 : 0) + l8;
    const int a_kof = (sel & 2) ? 4 : 0;
    //  B (.x4 per nt-pair): m0 n..n+7 k, m1 n k+4, m2 n+8 k, m3 n+8 k+4
    const int b_row = warp_n * 64 + ((sel & 2) ? 8 : 0) + l8;
    const int b_kof = (sel & 1) ? 4 : 0;

    float sacc[4] = {0.f, 0.f, 0.f, 0.f};

    for (int oc = 0; oc < 8; ++oc) {
        const int ob = oc * 128;
        __syncthreads();
        if (tid < 128) {
            qb_s[tid] = qp[ob + tid] + bv[ob + tid];
            vw_s[tid] = Vw[ob + tid];
        }

        float c[2][8][4];
        #pragma unroll
        for (int mt = 0; mt < 2; ++mt)
            #pragma unroll
            for (int nt = 0; nt < 8; ++nt)
                #pragma unroll
                for (int i = 0; i < 4; ++i) c[mt][nt][i] = 0.f;

        load_tile(As, vrow0, 0, tid);
        load_tile(Bs, Wv + (size_t)ob * H_DIM, 0, tid);
        cp_commit();

        for (int kt = 0; kt < H_DIM / BK; ++kt) {
            const int cur = kt & 1;
            if (kt + 1 < H_DIM / BK) {
                const int nxt = cur ^ 1;
                load_tile(As + nxt * ST_FLTS, vrow0, (kt + 1) * BK, tid);
                load_tile(Bs + nxt * ST_FLTS, Wv + (size_t)ob * H_DIM, (kt + 1) * BK, tid);
                cp_commit();
                cp_wait<1>();
            } else {
                cp_wait<0>();
            }
            __syncthreads();

            const uint32_t a_base = smem_u32(As + cur * ST_FLTS + a_row * LDP + a_kof);
            const uint32_t b_base = smem_u32(Bs + cur * ST_FLTS + b_row * LDP + b_kof);

            #pragma unroll
            for (int ks = 0; ks < 4; ++ks) {
                const uint32_t koff = ks * 32;   // 8 floats
                uint32_t af[2][4], bf[8][2];
                #pragma unroll
                for (int mt = 0; mt < 2; ++mt)
                    ldsm_x4(af[mt], a_base + mt * (16 * LDP * 4) + koff);
                #pragma unroll
                for (int np = 0; np < 4; ++np) {
                    uint32_t r[4];
                    ldsm_x4(r, b_base + np * (16 * LDP * 4) + koff);
                    bf[np * 2 + 0][0] = r[0];
                    bf[np * 2 + 0][1] = r[1];
                    bf[np * 2 + 1][0] = r[2];
                    bf[np * 2 + 1][1] = r[3];
                }
                #pragma unroll
                for (int mt = 0; mt < 2; ++mt)
                    #pragma unroll
                    for (int nt = 0; nt < 8; ++nt)
                        mma_tf32(c[mt][nt], af[mt], bf[nt]);
            }
            __syncthreads();
        }

        // Epilogue: tanh + Vw contraction into per-lane row partials
        #pragma unroll
        for (int nt = 0; nt < 8; ++nt) {
            const int col0 = warp_n * 64 + nt * 8 + 2 * tig;
            const float vw0 = vw_s[col0],     qb0 = qb_s[col0];
            const float vw1 = vw_s[col0 + 1], qb1 = qb_s[col0 + 1];
            #pragma unroll
            for (int mt = 0; mt < 2; ++mt) {
                sacc[mt * 2 + 0] += vw0 * fast_tanh(c[mt][nt][0] + qb0)
                                  + vw1 * fast_tanh(c[mt][nt][1] + qb1);
                sacc[mt * 2 + 1] += vw0 * fast_tanh(c[mt][nt][2] + qb0)
                                  + vw1 * fast_tanh(c[mt][nt][3] + qb1);
            }
        }
    }

    #pragma unroll
    for (int i = 0; i < 4; ++i) {
        sacc[i] += __shfl_xor_sync(0xffffffffu, sacc[i], 1);
        sacc[i] += __shfl_xor_sync(0xffffffffu, sacc[i], 2);
    }
    if (tig == 0) {
        #pragma unroll
        for (int i = 0; i < 4; ++i) {
            const int row = warp_m * 32 + (i >> 1) * 16 + gid + (i & 1) * 8;
            atomicAdd(&score_s[row], sacc[i]);
        }
    }
    __syncthreads();
    if (tid < 128) g_score[r0 + tid] = score_s[tid] + Vb[0];
}

// ---------------------------------------------------------------------------
// Kernel 3: softmax over T per batch. Writes weights into d_out[B*H ..].
// ---------------------------------------------------------------------------
__global__ void softmax_kernel(float* __restrict__ d_out) {
    __shared__ float red[1024];
    const int b = blockIdx.x;
    const int tid = threadIdx.x;
    const float s0 = g_score[b * T_DIM + tid];
    const float s1 = g_score[b * T_DIM + 1024 + tid];
    red[tid] = fmaxf(s0, s1);
    __syncthreads();
    for (int s = 512; s > 0; s >>= 1) {
        if (tid < s) red[tid] = fmaxf(red[tid], red[tid + s]);
        __syncthreads();
    }
    const float mx = red[0];
    __syncthreads();
    const float e0 = expf(s0 - mx), e1 = expf(s1 - mx);
    red[tid] = e0 + e1;
    __syncthreads();
    for (int s = 512; s > 0; s >>= 1) {
        if (tid < s) red[tid] += red[tid + s];
        __syncthreads();
    }
    const float inv = 1.f / red[0];
    float* w = d_out + B_DIM * H_DIM + b * T_DIM;
    w[tid] = e0 * inv;
    w[tid + 1024] = e1 * inv;
}

// ---------------------------------------------------------------------------
// Kernel 4a: context partials over T chunks; 4b: deterministic reduce.
// ---------------------------------------------------------------------------
__global__ void __launch_bounds__(1024) ctx_partial_kernel(
    const float* __restrict__ values, const float* __restrict__ d_out_w) {
    __shared__ float w_s[256];
    const int ts = blockIdx.x, b = blockIdx.y;
    const int h = threadIdx.x;
    const float* w = d_out_w + b * T_DIM + ts * 256;
    if (h < 256) w_s[h] = w[h];
    __syncthreads();
    const float* vp = values + ((size_t)b * T_DIM + ts * 256) * H_DIM + h;
    float a0 = 0.f, a1 = 0.f, a2 = 0.f, a3 = 0.f;
    #pragma unroll 4
    for (int t = 0; t < 256; t += 4) {
        a0 += w_s[t + 0] * vp[(size_t)(t + 0) * H_DIM];
        a1 += w_s[t + 1] * vp[(size_t)(t + 1) * H_DIM];
        a2 += w_s[t + 2] * vp[(size_t)(t + 2) * H_DIM];
        a3 += w_s[t + 3] * vp[(size_t)(t + 3) * H_DIM];
    }
    g_ctx_part[(b * 8 + ts) * H_DIM + h] = (a0 + a1) + (a2 + a3);
}

__global__ void __launch_bounds__(1024) ctx_reduce_kernel(float* __restrict__ d_out) {
    const int b = blockIdx.x, h = threadIdx.x;
    float s = 0.f;
    #pragma unroll
    for (int ts = 0; ts < 8; ++ts) s += g_ctx_part[(b * 8 + ts) * H_DIM + h];
    d_out[b * H_DIM + h] = s;
}

// ---------------------------------------------------------------------------
extern "C" void kernel_launch(void* const* d_in, const int* in_sizes, int n_in,
                              void* d_out, int out_size) {
    const float* query  = (const float*)d_in[0];
    const float* values = (const float*)d_in[1];
    const float* Wq     = (const float*)d_in[2];
    const float* bq     = (const float*)d_in[3];
    const float* Wv     = (const float*)d_in[4];
    const float* bv     = (const float*)d_in[5];
    const float* Vw     = (const float*)d_in[6];
    const float* Vb     = (const float*)d_in[7];
    float* out = (float*)d_out;

    cudaFuncSetAttribute(score_kernel, cudaFuncAttributeMaxDynamicSharedMemorySize,
                         SMEM_BYTES);

    qproj_kernel<<<B_DIM, 256>>>(query, Wq, bq);
    score_kernel<<<(B_DIM * T_DIM) / 128, 256, SMEM_BYTES>>>(values, Wv, bv, Vw, Vb);
    softmax_kernel<<<B_DIM, 1024>>>(out);
    ctx_partial_kernel<<<dim3(8, B_DIM), 1024>>>(values, out + B_DIM * H_DIM);
    ctx_reduce_kernel<<<B_DIM, 1024>>>(out);
}